// round 5
// baseline (speedup 1.0000x reference)
#include <cuda_runtime.h>
#include <cstdint>

// MaxUnpooling2D: updates [16,64,64,256] f32, mask [16,64,64,256] i32
// (flattened per-batch output index), out [16,128,128,256] f32.
//
// Each pooled element scatters into its OWN 2x2 window at the SAME channel
// => output cells are covered exactly once. Fused zero-fill + scatter:
// each thread owns 8 channels (2x float4) of one pooled element and writes
// all 4 window cells (selected value or zero). Dense, coalesced, no atomics.
//
// R2: 2x work per thread (MLP_p1 2->4), streaming cache hints (zero reuse).
// R3: fix decode shifts for 8-channel groups (bits: c8:5 w:6 h:6 b:4).
// R4: resubmit (round 4 bench was an infra container failure).

#define C_  256
#define WO_ 128
#define HOWOC_ (128 * 128 * 256)   // per-batch output elements

__global__ void __launch_bounds__(256) max_unpool_kernel(
    const float4* __restrict__ upd,
    const int4*   __restrict__ msk,
    float*        __restrict__ out,
    int n8)
{
    int t = blockIdx.x * blockDim.x + threadIdx.x;
    if (t >= n8) return;

    // Front-batch all 4 loads (64 B per thread) for max MLP.
    int4   m0 = __ldcs(msk + 2 * t);
    int4   m1 = __ldcs(msk + 2 * t + 1);
    float4 u0 = __ldcs(upd + 2 * t);
    float4 u1 = __ldcs(upd + 2 * t + 1);

    // Decode coords from linear 8-channel-group index.
    // Bit layout of t: c8 [0,5), w [5,11), h [11,17), b [17,21).
    int c8 = t & 31;
    int w  = (t >> 5)  & 63;
    int h  = (t >> 11) & 63;
    int b  = t >> 17;

    // Per-batch flattened address of window cell (0,0), channel 8*c8.
    int base = h * (2 * WO_ * C_) + w * (2 * C_) + (c8 << 3);

    float* ob = out + (size_t)b * HOWOC_ + base;

    // Window-cell offsets: (di*Wo + dj)*C for (di,dj) in {0,1}^2.
    const int offs[4] = {0, C_, WO_ * C_, WO_ * C_ + C_};

#pragma unroll
    for (int k = 0; k < 4; k++) {
        int a = base + offs[k];
        float4 v0, v1;
        v0.x = (m0.x == a + 0) ? u0.x : 0.0f;
        v0.y = (m0.y == a + 1) ? u0.y : 0.0f;
        v0.z = (m0.z == a + 2) ? u0.z : 0.0f;
        v0.w = (m0.w == a + 3) ? u0.w : 0.0f;
        v1.x = (m1.x == a + 4) ? u1.x : 0.0f;
        v1.y = (m1.y == a + 5) ? u1.y : 0.0f;
        v1.z = (m1.z == a + 6) ? u1.z : 0.0f;
        v1.w = (m1.w == a + 7) ? u1.w : 0.0f;
        __stcs(reinterpret_cast<float4*>(ob + offs[k]),     v0);
        __stcs(reinterpret_cast<float4*>(ob + offs[k]) + 1, v1);
    }
}

extern "C" void kernel_launch(void* const* d_in, const int* in_sizes, int n_in,
                              void* d_out, int out_size)
{
    const float4* upd = (const float4*)d_in[0];
    const int4*   msk = (const int4*)d_in[1];
    float*        out = (float*)d_out;

    int n  = in_sizes[0];       // 16*64*64*256 = 16,777,216
    int n8 = n >> 3;            // 2,097,152 work items (8 channels each)

    int threads = 256;
    int blocks  = (n8 + threads - 1) / threads;   // 8192
    max_unpool_kernel<<<blocks, threads>>>(upd, msk, out, n8);
}

// round 6
// speedup vs baseline: 1.1916x; 1.1916x over previous
#include <cuda_runtime.h>
#include <cstdint>

// MaxUnpooling2D: updates [16,64,64,256] f32, mask [16,64,64,256] i32
// (flattened per-batch output index), out [16,128,128,256] f32.
//
// Each pooled element scatters into its OWN 2x2 window at the SAME channel
// => output cells are covered exactly once. Fused zero-fill + scatter.
//
// R6: MLP=4 with FULL coalescing — thread t handles float4 groups t and
// t + n4/2 (far split), so every warp load/store is a dense 512B burst
// (R5's 2t/2t+1 interleave halved per-instruction density -> L1-bound).
// No cache hints (isolate the variable; R1 baseline was 72% DRAM without).

#define C_  256
#define WO_ 128
#define HOWOC_ (128 * 128 * 256)   // per-batch output elements

__device__ __forceinline__ void scatter_one(
    const int4& m, const float4& u, int e, float* __restrict__ out)
{
    // Decode float4-group index e: c4 [0,6), w [6,12), h [12,18), b [18,22).
    int c4 = e & 63;
    int w  = (e >> 6)  & 63;
    int h  = (e >> 12) & 63;
    int b  = e >> 18;

    int base = h * (2 * WO_ * C_) + w * (2 * C_) + (c4 << 2);
    float* ob = out + (size_t)b * HOWOC_ + base;

    const int offs[4] = {0, C_, WO_ * C_, WO_ * C_ + C_};
#pragma unroll
    for (int k = 0; k < 4; k++) {
        int a = base + offs[k];
        float4 v;
        v.x = (m.x == a + 0) ? u.x : 0.0f;
        v.y = (m.y == a + 1) ? u.y : 0.0f;
        v.z = (m.z == a + 2) ? u.z : 0.0f;
        v.w = (m.w == a + 3) ? u.w : 0.0f;
        *reinterpret_cast<float4*>(ob + offs[k]) = v;
    }
}

__global__ void __launch_bounds__(256) max_unpool_kernel(
    const float4* __restrict__ upd,
    const int4*   __restrict__ msk,
    float*        __restrict__ out,
    int half)
{
    int t = blockIdx.x * blockDim.x + threadIdx.x;
    if (t >= half) return;
    int t2 = t + half;

    // Front-batch all 4 loads (independent, each instruction fully coalesced).
    int4   m0 = msk[t];
    int4   m1 = msk[t2];
    float4 u0 = upd[t];
    float4 u1 = upd[t2];

    scatter_one(m0, u0, t,  out);
    scatter_one(m1, u1, t2, out);
}

extern "C" void kernel_launch(void* const* d_in, const int* in_sizes, int n_in,
                              void* d_out, int out_size)
{
    const float4* upd = (const float4*)d_in[0];
    const int4*   msk = (const int4*)d_in[1];
    float*        out = (float*)d_out;

    int n    = in_sizes[0];   // 16*64*64*256 = 16,777,216
    int n4   = n >> 2;        // 4,194,304 float4 groups
    int half = n4 >> 1;       // 2,097,152 threads

    int threads = 256;
    int blocks  = (half + threads - 1) / threads;   // 8192
    max_unpool_kernel<<<blocks, threads>>>(upd, msk, out, half);
}

// round 7
// speedup vs baseline: 1.2097x; 1.0152x over previous
#include <cuda_runtime.h>
#include <cstdint>

// MaxUnpooling2D: updates [16,64,64,256] f32, mask [16,64,64,256] i32
// (flattened per-batch output index), out [16,128,128,256] f32.
//
// Each pooled element scatters into its OWN 2x2 window at the SAME channel
// => output cells are covered exactly once by the union of all
// (thread, window-cell) stores. Fused zero-fill + scatter: each thread owns
// 4 channels of one pooled element and writes all 4 window cells as float4
// (selected value or zero). Fully dense, fully coalesced.
//
// R7: exact R1 structure (best so far: 65.5us, DRAM 72%) + streaming cache
// hints ONLY (__ldcs/__stcs). Zero-reuse streams -> evict-first keeps L2
// clean for write-burst coalescing. R5/R6 showed extra per-thread MLP does
// not help (not latency-limited), so this isolates the cache-policy lever.

#define C_  256
#define WO_ 128
#define HOWOC_ (128 * 128 * 256)   // per-batch output elements

__global__ void __launch_bounds__(256) max_unpool_kernel(
    const float4* __restrict__ upd,
    const int4*   __restrict__ msk,
    float*        __restrict__ out,
    int n4)
{
    int t = blockIdx.x * blockDim.x + threadIdx.x;
    if (t >= n4) return;

    int4   m = __ldcs(msk + t);
    float4 u = __ldcs(upd + t);

    // Decode coords from linear float4 index. C/4 = 64, W = 64, H = 64.
    int c4 = t & 63;
    int w  = (t >> 6) & 63;
    int h  = (t >> 12) & 63;
    int b  = t >> 18;

    // Per-batch flattened base address of window cell (di=0, dj=0), channel 4*c4.
    int base = h * (2 * WO_ * C_) + w * (2 * C_) + (c4 << 2);

    float* ob = out + (size_t)b * HOWOC_ + base;

    // Window-cell offsets: (di*Wo + dj)*C for (di,dj) in {0,1}^2.
    const int offs[4] = {0, C_, WO_ * C_, WO_ * C_ + C_};

#pragma unroll
    for (int k = 0; k < 4; k++) {
        int a = base + offs[k];
        float4 v;
        v.x = (m.x == a + 0) ? u.x : 0.0f;
        v.y = (m.y == a + 1) ? u.y : 0.0f;
        v.z = (m.z == a + 2) ? u.z : 0.0f;
        v.w = (m.w == a + 3) ? u.w : 0.0f;
        __stcs(reinterpret_cast<float4*>(ob + offs[k]), v);
    }
}

extern "C" void kernel_launch(void* const* d_in, const int* in_sizes, int n_in,
                              void* d_out, int out_size)
{
    const float4* upd = (const float4*)d_in[0];
    const int4*   msk = (const int4*)d_in[1];
    float*        out = (float*)d_out;

    int n  = in_sizes[0];       // 16*64*64*256 = 16,777,216
    int n4 = n >> 2;            // 4,194,304 float4 work items

    int threads = 256;
    int blocks  = (n4 + threads - 1) / threads;   // 16384
    max_unpool_kernel<<<blocks, threads>>>(upd, msk, out, n4);
}